// round 2
// baseline (speedup 1.0000x reference)
#include <cuda_runtime.h>

#define POOLED 7
#define KSIZE  2
#define CROP   (POOLED * KSIZE)   // 14
#define HH     50
#define WW     50
#define CC     512
#define C4     (CC / 4)           // 128 float4 per pixel
#define NROI   256

__device__ __forceinline__ float4 lerp4(float4 a, float4 b, float w) {
    float4 r;
    r.x = a.x + (b.x - a.x) * w;
    r.y = a.y + (b.y - a.y) * w;
    r.z = a.z + (b.z - a.z) * w;
    r.w = a.w + (b.w - a.w) * w;
    return r;
}

struct RowX {
    float4 v00, v01, v10, v11;   // values at columns c00, c01, c10, c11
};

// Load one feature row's 4 corner columns with dedup.
// p points at (row, col=0, c4) for this thread. Column offsets are in units
// of C4 float4s. All branch conditions are block-uniform -> no divergence.
__device__ __forceinline__ RowX load_rowx(const float4* __restrict__ p,
                                          int c00, int c01, int c10, int c11) {
    RowX r;
    r.v00 = p[c00 * C4];
    r.v01 = (c01 == c00) ? r.v00 : p[c01 * C4];
    if (c10 == c00) {                 // second sample in same cell -> c11==c01
        r.v10 = r.v00; r.v11 = r.v01;
    } else if (c10 == c01) {          // overlap by one column (sx forward)
        r.v10 = r.v01;
        r.v11 = (c11 == c10) ? r.v10 : p[c11 * C4];
    } else if (c11 == c00) {          // overlap by one column (sx backward)
        r.v11 = r.v00;
        r.v10 = p[c10 * C4];
    } else {                          // disjoint
        r.v10 = p[c10 * C4];
        r.v11 = (c11 == c10) ? r.v10 : p[c11 * C4];
    }
    return r;
}

__global__ __launch_bounds__(128)
void roi_pool_kernel(const float* __restrict__ fm,
                     const float* __restrict__ rois,
                     float* __restrict__ out) {
    const int cell = blockIdx.x;            // 0 .. 256*49-1
    const int n  = cell / (POOLED * POOLED);
    const int pp = cell - n * (POOLED * POOLED);
    const int ph = pp / POOLED;
    const int pw = pp - ph * POOLED;
    const int b  = n >> 7;

    // rois flat: n*4 + {0:x1, 1:y1, 2:x2, 3:y2}
    const float rx1 = __ldg(&rois[n * 4 + 0]);
    const float ry1 = __ldg(&rois[n * 4 + 1]);
    const float rx2 = __ldg(&rois[n * 4 + 2]);
    const float ry2 = __ldg(&rois[n * 4 + 3]);

    const float sy = (ry2 - ry1) * (float)(HH - 1) / (float)(CROP - 1);
    const float sx = (rx2 - rx1) * (float)(WW - 1) / (float)(CROP - 1);
    const float by = ry1 * (float)(HH - 1);
    const float bx = rx1 * (float)(WW - 1);

    int   y0i[KSIZE], y1i[KSIZE];
    float wy[KSIZE];
    bool  vy[KSIZE];
#pragma unroll
    for (int ky = 0; ky < KSIZE; ky++) {
        const float i  = (float)(KSIZE * ph + ky);
        const float ys = by + i * sy;
        vy[ky] = (ys >= 0.0f) && (ys <= (float)(HH - 1));
        const float y0f = floorf(ys);
        wy[ky] = ys - y0f;
        int y0 = (int)y0f;
        y0 = min(max(y0, 0), HH - 1);
        y0i[ky] = y0;
        y1i[ky] = min(y0 + 1, HH - 1);
    }

    int   x0i[KSIZE], x1i[KSIZE];
    float wx[KSIZE];
    bool  vx[KSIZE];
#pragma unroll
    for (int kx = 0; kx < KSIZE; kx++) {
        const float j  = (float)(KSIZE * pw + kx);
        const float xs = bx + j * sx;
        vx[kx] = (xs >= 0.0f) && (xs <= (float)(WW - 1));
        const float x0f = floorf(xs);
        wx[kx] = xs - x0f;
        int x0 = (int)x0f;
        x0 = min(max(x0, 0), WW - 1);
        x0i[kx] = x0;
        x1i[kx] = min(x0 + 1, WW - 1);
    }

    const int c4 = threadIdx.x;
    const float4* __restrict__ fmv = (const float4*)fm;
    // thread-local base at (b, row=0, col=0, c4), 32-bit offsets throughout
    const float4* __restrict__ base = fmv + b * (HH * WW * C4) + c4;

    const int c00 = x0i[0], c01 = x1i[0], c10 = x0i[1], c11 = x1i[1];
    const int R00 = y0i[0], R01 = y1i[0], R10 = y0i[1], R11 = y1i[1];

    // ---- ky = 0 rows (with row dedup R01 vs R00) ----
    RowX a = load_rowx(base + R00 * (WW * C4), c00, c01, c10, c11);
    RowX bR;
    if (R01 == R00) bR = a;
    else            bR = load_rowx(base + R01 * (WW * C4), c00, c01, c10, c11);

    float4 best;
    best.x = best.y = best.z = best.w = -__FLT_MAX__;

    {
        // window (ky=0, kx=0)
        float4 t0 = lerp4(a.v00, bR.v00, wy[0]);
        float4 t1 = lerp4(a.v01, bR.v01, wy[0]);
        float4 v  = lerp4(t0, t1, wx[0]);
        if (!(vy[0] && vx[0])) { v.x = v.y = v.z = v.w = 0.0f; }
        best.x = fmaxf(best.x, v.x); best.y = fmaxf(best.y, v.y);
        best.z = fmaxf(best.z, v.z); best.w = fmaxf(best.w, v.w);
        // window (ky=0, kx=1)
        t0 = lerp4(a.v10, bR.v10, wy[0]);
        t1 = lerp4(a.v11, bR.v11, wy[0]);
        v  = lerp4(t0, t1, wx[1]);
        if (!(vy[0] && vx[1])) { v.x = v.y = v.z = v.w = 0.0f; }
        best.x = fmaxf(best.x, v.x); best.y = fmaxf(best.y, v.y);
        best.z = fmaxf(best.z, v.z); best.w = fmaxf(best.w, v.w);
    }

    // ---- ky = 1 rows (dedup against ky=0 rows) ----
    RowX c;
    if      (R10 == R00) c = a;
    else if (R10 == R01) c = bR;
    else                 c = load_rowx(base + R10 * (WW * C4), c00, c01, c10, c11);
    RowX d;
    if      (R11 == R01) d = bR;
    else if (R11 == R00) d = a;
    else if (R11 == R10) d = c;
    else                 d = load_rowx(base + R11 * (WW * C4), c00, c01, c10, c11);

    {
        // window (ky=1, kx=0)
        float4 t0 = lerp4(c.v00, d.v00, wy[1]);
        float4 t1 = lerp4(c.v01, d.v01, wy[1]);
        float4 v  = lerp4(t0, t1, wx[0]);
        if (!(vy[1] && vx[0])) { v.x = v.y = v.z = v.w = 0.0f; }
        best.x = fmaxf(best.x, v.x); best.y = fmaxf(best.y, v.y);
        best.z = fmaxf(best.z, v.z); best.w = fmaxf(best.w, v.w);
        // window (ky=1, kx=1)
        t0 = lerp4(c.v10, d.v10, wy[1]);
        t1 = lerp4(c.v11, d.v11, wy[1]);
        v  = lerp4(t0, t1, wx[1]);
        if (!(vy[1] && vx[1])) { v.x = v.y = v.z = v.w = 0.0f; }
        best.x = fmaxf(best.x, v.x); best.y = fmaxf(best.y, v.y);
        best.z = fmaxf(best.z, v.z); best.w = fmaxf(best.w, v.w);
    }

    ((float4*)out)[cell * C4 + c4] = best;
}

extern "C" void kernel_launch(void* const* d_in, const int* in_sizes, int n_in,
                              void* d_out, int out_size) {
    const float* fm   = (const float*)d_in[0];   // (2,50,50,512) f32
    const float* rois = (const float*)d_in[1];   // (2,128,4) f32
    float* out = (float*)d_out;                  // (256,7,7,512) f32

    const int blocks = NROI * POOLED * POOLED;   // 12544
    roi_pool_kernel<<<blocks, 128>>>(fm, rois, out);
}

// round 3
// speedup vs baseline: 1.5466x; 1.5466x over previous
#include <cuda_runtime.h>

#define POOLED 7
#define KSIZE  2
#define CROP   (POOLED * KSIZE)   // 14
#define HH     50
#define WW     50
#define CC     512
#define C4     (CC / 4)           // 128 16-byte groups per pixel
#define NROI   256

typedef unsigned long long u64;

// ---- packed f32x2 helpers (sm_103a) ----
__device__ __forceinline__ u64 pack2(float v) {
    u64 r; asm("mov.b64 %0, {%1, %1};" : "=l"(r) : "f"(v)); return r;
}
__device__ __forceinline__ u64 mul2(u64 a, u64 b) {
    u64 r; asm("mul.rn.f32x2 %0, %1, %2;" : "=l"(r) : "l"(a), "l"(b)); return r;
}
__device__ __forceinline__ u64 fma2(u64 a, u64 b, u64 c) {
    u64 r; asm("fma.rn.f32x2 %0, %1, %2, %3;" : "=l"(r) : "l"(a), "l"(b), "l"(c)); return r;
}
__device__ __forceinline__ void unpack2(u64 v, float& lo, float& hi) {
    asm("mov.b64 {%0, %1}, %2;" : "=f"(lo), "=f"(hi) : "l"(v));
}
// lerp(a,b,w) computed as a*(1-w) + b*w  (uw = 1-w precomputed & packed)
__device__ __forceinline__ u64 lerp2(u64 a, u64 b, u64 uw, u64 w) {
    return fma2(a, uw, mul2(b, w));
}

__global__ void __launch_bounds__(128, 8)
roi_pool_kernel(const float* __restrict__ fm,
                const float* __restrict__ rois,
                float* __restrict__ out) {
    const int blk = blockIdx.x;             // 0 .. 256*7-1  = n*7 + ph
    const int n  = blk / POOLED;
    const int ph = blk - n * POOLED;
    const int b  = n >> 7;

    // rois flat: n*4 + {0:x1, 1:y1, 2:x2, 3:y2} (after reference's [1,0,3,2] perm)
    const float4 rr = __ldg((const float4*)(rois) + n);
    const float rx1 = rr.x, ry1 = rr.y, rx2 = rr.z, ry2 = rr.w;

    const float sy = (ry2 - ry1) * (float)(HH - 1) / (float)(CROP - 1);
    const float sx = (rx2 - rx1) * (float)(WW - 1) / (float)(CROP - 1);
    const float by = ry1 * (float)(HH - 1);
    const float bx = rx1 * (float)(WW - 1);

    // ---- per-(n,ph) y setup (amortized over 7 pw cells) ----
    int   y0i[KSIZE], y1i[KSIZE];
    float wyf[KSIZE];
    bool  vy[KSIZE];
#pragma unroll
    for (int ky = 0; ky < KSIZE; ky++) {
        const float i  = (float)(KSIZE * ph + ky);
        const float ys = by + i * sy;
        vy[ky] = (ys >= 0.0f) && (ys <= (float)(HH - 1));
        const float y0f = floorf(ys);
        wyf[ky] = ys - y0f;
        int y0 = (int)y0f;
        y0 = min(max(y0, 0), HH - 1);
        y0i[ky] = y0;
        y1i[ky] = min(y0 + 1, HH - 1);
    }
    u64 wy2[KSIZE], uy2[KSIZE];
#pragma unroll
    for (int ky = 0; ky < KSIZE; ky++) {
        wy2[ky] = pack2(wyf[ky]);
        uy2[ky] = pack2(1.0f - wyf[ky]);
    }

    const int c4 = threadIdx.x;
    // thread base at (b, row 0, col 0, channel group c4); each pixel = C4 ulonglong2
    const ulonglong2* __restrict__ base =
        (const ulonglong2*)fm + b * (HH * WW * C4) + c4;
    const ulonglong2* __restrict__ rp[4];   // rows: [ky0:y0, ky0:y1, ky1:y0, ky1:y1]
    rp[0] = base + y0i[0] * (WW * C4);
    rp[1] = base + y1i[0] * (WW * C4);
    rp[2] = base + y0i[1] * (WW * C4);
    rp[3] = base + y1i[1] * (WW * C4);

    float4* __restrict__ outp =
        (float4*)out + (n * (POOLED * POOLED) + ph * POOLED) * C4 + c4;

#pragma unroll 1
    for (int pw = 0; pw < POOLED; pw++) {
        // ---- per-pw x setup ----
        int   x0i[KSIZE], x1i[KSIZE];
        u64   wx2[KSIZE], ux2[KSIZE];
        bool  vx[KSIZE];
#pragma unroll
        for (int kx = 0; kx < KSIZE; kx++) {
            const float j  = (float)(KSIZE * pw + kx);
            const float xs = bx + j * sx;
            vx[kx] = (xs >= 0.0f) && (xs <= (float)(WW - 1));
            const float x0f = floorf(xs);
            const float w   = xs - x0f;
            wx2[kx] = pack2(w);
            ux2[kx] = pack2(1.0f - w);
            int x0 = (int)x0f;
            x0 = min(max(x0, 0), WW - 1);
            x0i[kx] = x0;
            x1i[kx] = min(x0 + 1, WW - 1);
        }

        float bx0 = -__FLT_MAX__, bx1 = -__FLT_MAX__,
              bx2 = -__FLT_MAX__, bx3 = -__FLT_MAX__;

        // ---- process each ky: 8 independent loads, 2 windows ----
#pragma unroll
        for (int ky = 0; ky < KSIZE; ky++) {
            const ulonglong2* ra = rp[2 * ky];       // y0 row
            const ulonglong2* rb = rp[2 * ky + 1];   // y1 row
            // 8 independent 16B loads
            ulonglong2 a0 = ra[x0i[0] * C4];
            ulonglong2 a1 = ra[x1i[0] * C4];
            ulonglong2 a2 = ra[x0i[1] * C4];
            ulonglong2 a3 = ra[x1i[1] * C4];
            ulonglong2 b0 = rb[x0i[0] * C4];
            ulonglong2 b1 = rb[x1i[0] * C4];
            ulonglong2 b2 = rb[x0i[1] * C4];
            ulonglong2 b3 = rb[x1i[1] * C4];

#pragma unroll
            for (int kx = 0; kx < KSIZE; kx++) {
                const ulonglong2 &p0 = (kx == 0) ? a0 : a2;  // y0,x0
                const ulonglong2 &p1 = (kx == 0) ? a1 : a3;  // y0,x1
                const ulonglong2 &q0 = (kx == 0) ? b0 : b2;  // y1,x0
                const ulonglong2 &q1 = (kx == 0) ? b1 : b3;  // y1,x1
                // y-lerp then x-lerp (reference order), packed 2-wide
                u64 t0l = lerp2(p0.x, q0.x, uy2[ky], wy2[ky]);
                u64 t0h = lerp2(p0.y, q0.y, uy2[ky], wy2[ky]);
                u64 t1l = lerp2(p1.x, q1.x, uy2[ky], wy2[ky]);
                u64 t1h = lerp2(p1.y, q1.y, uy2[ky], wy2[ky]);
                u64 vl  = lerp2(t0l, t1l, ux2[kx], wx2[kx]);
                u64 vh  = lerp2(t0h, t1h, ux2[kx], wx2[kx]);
                const bool valid = vy[ky] && vx[kx];
                vl = valid ? vl : 0ull;
                vh = valid ? vh : 0ull;
                float f0, f1, f2, f3;
                unpack2(vl, f0, f1);
                unpack2(vh, f2, f3);
                bx0 = fmaxf(bx0, f0);
                bx1 = fmaxf(bx1, f1);
                bx2 = fmaxf(bx2, f2);
                bx3 = fmaxf(bx3, f3);
            }
        }

        float4 res;
        res.x = bx0; res.y = bx1; res.z = bx2; res.w = bx3;
        outp[pw * C4] = res;
    }
}

extern "C" void kernel_launch(void* const* d_in, const int* in_sizes, int n_in,
                              void* d_out, int out_size) {
    const float* fm   = (const float*)d_in[0];   // (2,50,50,512) f32
    const float* rois = (const float*)d_in[1];   // (2,128,4) f32
    float* out = (float*)d_out;                  // (256,7,7,512) f32

    const int blocks = NROI * POOLED;            // 1792
    roi_pool_kernel<<<blocks, 128>>>(fm, rois, out);
}

// round 4
// speedup vs baseline: 1.6093x; 1.0405x over previous
#include <cuda_runtime.h>

#define POOLED 7
#define KSIZE  2
#define CROP   (POOLED * KSIZE)   // 14
#define HH     50
#define WW     50
#define CC     512
#define C4     (CC / 4)           // 128 16-byte groups per pixel
#define NROI   256

typedef unsigned long long u64;

// ---- packed f32x2 helpers (sm_103a) ----
__device__ __forceinline__ u64 pack2(float v) {
    u64 r; asm("mov.b64 %0, {%1, %1};" : "=l"(r) : "f"(v)); return r;
}
__device__ __forceinline__ u64 mul2(u64 a, u64 b) {
    u64 r; asm("mul.rn.f32x2 %0, %1, %2;" : "=l"(r) : "l"(a), "l"(b)); return r;
}
__device__ __forceinline__ u64 fma2(u64 a, u64 b, u64 c) {
    u64 r; asm("fma.rn.f32x2 %0, %1, %2, %3;" : "=l"(r) : "l"(a), "l"(b), "l"(c)); return r;
}
__device__ __forceinline__ void unpack2(u64 v, float& lo, float& hi) {
    asm("mov.b64 {%0, %1}, %2;" : "=f"(lo), "=f"(hi) : "l"(v));
}
// lerp(a,b,w) = a*uw + b*w, with uw = (1-w) premasked by validity
__device__ __forceinline__ u64 lerp2(u64 a, u64 b, u64 uw, u64 w) {
    return fma2(a, uw, mul2(b, w));
}

__global__ void __launch_bounds__(128)
roi_pool_kernel(const float* __restrict__ fm,
                const float* __restrict__ rois,
                float* __restrict__ out) {
    const int cell = blockIdx.x;            // 0 .. 256*49-1
    const int n  = cell / (POOLED * POOLED);
    const int pp = cell - n * (POOLED * POOLED);
    const int ph = pp / POOLED;
    const int pw = pp - ph * POOLED;
    const int b  = n >> 7;

    // rois flat: n*4 + {0:x1, 1:y1, 2:x2, 3:y2} (after reference's [1,0,3,2] perm)
    const float4 rr = __ldg((const float4*)rois + n);
    const float sy = (rr.w - rr.y) * (float)(HH - 1) / (float)(CROP - 1);
    const float sx = (rr.z - rr.x) * (float)(WW - 1) / (float)(CROP - 1);
    const float by = rr.y * (float)(HH - 1);
    const float bx = rr.x * (float)(WW - 1);

    // ---- y setup (validity folded into packed weights) ----
    int y0i[KSIZE], y1i[KSIZE];
    u64 wy2[KSIZE], uy2[KSIZE];
#pragma unroll
    for (int ky = 0; ky < KSIZE; ky++) {
        const float i  = (float)(KSIZE * ph + ky);
        const float ys = by + i * sy;
        const float m  = ((ys >= 0.0f) && (ys <= (float)(HH - 1))) ? 1.0f : 0.0f;
        const float y0f = floorf(ys);
        const float w   = ys - y0f;
        wy2[ky] = pack2(w * m);
        uy2[ky] = pack2((1.0f - w) * m);
        int y0 = (int)y0f;
        y0 = min(max(y0, 0), HH - 1);
        y0i[ky] = y0;
        y1i[ky] = min(y0 + 1, HH - 1);
    }

    // ---- x setup ----
    int x0i[KSIZE], x1i[KSIZE];
    u64 wx2[KSIZE], ux2[KSIZE];
#pragma unroll
    for (int kx = 0; kx < KSIZE; kx++) {
        const float j  = (float)(KSIZE * pw + kx);
        const float xs = bx + j * sx;
        const float m  = ((xs >= 0.0f) && (xs <= (float)(WW - 1))) ? 1.0f : 0.0f;
        const float x0f = floorf(xs);
        const float w   = xs - x0f;
        wx2[kx] = pack2(w * m);
        ux2[kx] = pack2((1.0f - w) * m);
        int x0 = (int)x0f;
        x0 = min(max(x0, 0), WW - 1);
        x0i[kx] = x0;
        x1i[kx] = min(x0 + 1, WW - 1);
    }

    const int c4 = threadIdx.x;
    const ulonglong2* __restrict__ base =
        (const ulonglong2*)fm + b * (HH * WW * C4) + c4;
    // 4 row bases (32-bit offsets), 4 column offsets
    const int r0 = y0i[0] * (WW * C4);
    const int r1 = y1i[0] * (WW * C4);
    const int r2 = y0i[1] * (WW * C4);
    const int r3 = y1i[1] * (WW * C4);
    const int o0 = x0i[0] * C4;
    const int o1 = x1i[0] * C4;
    const int o2 = x0i[1] * C4;
    const int o3 = x1i[1] * C4;

    // ---- 16 independent 16B loads, all up front (MLP=16) ----
    ulonglong2 p00 = base[r0 + o0];   // ky0: y0 row, x corners of kx0/kx1
    ulonglong2 p01 = base[r0 + o1];
    ulonglong2 p02 = base[r0 + o2];
    ulonglong2 p03 = base[r0 + o3];
    ulonglong2 p10 = base[r1 + o0];   // ky0: y1 row
    ulonglong2 p11 = base[r1 + o1];
    ulonglong2 p12 = base[r1 + o2];
    ulonglong2 p13 = base[r1 + o3];
    ulonglong2 p20 = base[r2 + o0];   // ky1: y0 row
    ulonglong2 p21 = base[r2 + o1];
    ulonglong2 p22 = base[r2 + o2];
    ulonglong2 p23 = base[r2 + o3];
    ulonglong2 p30 = base[r3 + o0];   // ky1: y1 row
    ulonglong2 p31 = base[r3 + o1];
    ulonglong2 p32 = base[r3 + o2];
    ulonglong2 p33 = base[r3 + o3];

    float b0 = -__FLT_MAX__, b1 = -__FLT_MAX__,
          b2 = -__FLT_MAX__, b3 = -__FLT_MAX__;

    // window (ky, kx): y-lerp rows then x-lerp (masked weights make invalid -> 0)
    {   // ky0 kx0
        u64 t0l = lerp2(p00.x, p10.x, uy2[0], wy2[0]);
        u64 t0h = lerp2(p00.y, p10.y, uy2[0], wy2[0]);
        u64 t1l = lerp2(p01.x, p11.x, uy2[0], wy2[0]);
        u64 t1h = lerp2(p01.y, p11.y, uy2[0], wy2[0]);
        u64 vl  = lerp2(t0l, t1l, ux2[0], wx2[0]);
        u64 vh  = lerp2(t0h, t1h, ux2[0], wx2[0]);
        float f0, f1, f2, f3;
        unpack2(vl, f0, f1); unpack2(vh, f2, f3);
        b0 = fmaxf(b0, f0); b1 = fmaxf(b1, f1);
        b2 = fmaxf(b2, f2); b3 = fmaxf(b3, f3);
    }
    {   // ky0 kx1
        u64 t0l = lerp2(p02.x, p12.x, uy2[0], wy2[0]);
        u64 t0h = lerp2(p02.y, p12.y, uy2[0], wy2[0]);
        u64 t1l = lerp2(p03.x, p13.x, uy2[0], wy2[0]);
        u64 t1h = lerp2(p03.y, p13.y, uy2[0], wy2[0]);
        u64 vl  = lerp2(t0l, t1l, ux2[1], wx2[1]);
        u64 vh  = lerp2(t0h, t1h, ux2[1], wx2[1]);
        float f0, f1, f2, f3;
        unpack2(vl, f0, f1); unpack2(vh, f2, f3);
        b0 = fmaxf(b0, f0); b1 = fmaxf(b1, f1);
        b2 = fmaxf(b2, f2); b3 = fmaxf(b3, f3);
    }
    {   // ky1 kx0
        u64 t0l = lerp2(p20.x, p30.x, uy2[1], wy2[1]);
        u64 t0h = lerp2(p20.y, p30.y, uy2[1], wy2[1]);
        u64 t1l = lerp2(p21.x, p31.x, uy2[1], wy2[1]);
        u64 t1h = lerp2(p21.y, p31.y, uy2[1], wy2[1]);
        u64 vl  = lerp2(t0l, t1l, ux2[0], wx2[0]);
        u64 vh  = lerp2(t0h, t1h, ux2[0], wx2[0]);
        float f0, f1, f2, f3;
        unpack2(vl, f0, f1); unpack2(vh, f2, f3);
        b0 = fmaxf(b0, f0); b1 = fmaxf(b1, f1);
        b2 = fmaxf(b2, f2); b3 = fmaxf(b3, f3);
    }
    {   // ky1 kx1
        u64 t0l = lerp2(p22.x, p32.x, uy2[1], wy2[1]);
        u64 t0h = lerp2(p22.y, p32.y, uy2[1], wy2[1]);
        u64 t1l = lerp2(p23.x, p33.x, uy2[1], wy2[1]);
        u64 t1h = lerp2(p23.y, p33.y, uy2[1], wy2[1]);
        u64 vl  = lerp2(t0l, t1l, ux2[1], wx2[1]);
        u64 vh  = lerp2(t0h, t1h, ux2[1], wx2[1]);
        float f0, f1, f2, f3;
        unpack2(vl, f0, f1); unpack2(vh, f2, f3);
        b0 = fmaxf(b0, f0); b1 = fmaxf(b1, f1);
        b2 = fmaxf(b2, f2); b3 = fmaxf(b3, f3);
    }

    float4 res;
    res.x = b0; res.y = b1; res.z = b2; res.w = b3;
    ((float4*)out)[cell * C4 + c4] = res;
}

extern "C" void kernel_launch(void* const* d_in, const int* in_sizes, int n_in,
                              void* d_out, int out_size) {
    const float* fm   = (const float*)d_in[0];   // (2,50,50,512) f32
    const float* rois = (const float*)d_in[1];   // (2,128,4) f32
    float* out = (float*)d_out;                  // (256,7,7,512) f32

    const int blocks = NROI * POOLED * POOLED;   // 12544
    roi_pool_kernel<<<blocks, 128>>>(fm, rois, out);
}

// round 5
// speedup vs baseline: 1.6772x; 1.0422x over previous
#include <cuda_runtime.h>

#define POOLED 7
#define KSIZE  2
#define CROP   (POOLED * KSIZE)   // 14
#define HH     50
#define WW     50
#define CC     512
#define C4     (CC / 4)           // 128 16-byte groups per pixel
#define NROI   256

typedef unsigned long long u64;

// ---- packed f32x2 helpers (sm_103a) ----
__device__ __forceinline__ u64 pack2(float v) {
    u64 r; asm("mov.b64 %0, {%1, %1};" : "=l"(r) : "f"(v)); return r;
}
__device__ __forceinline__ u64 mul2(u64 a, u64 b) {
    u64 r; asm("mul.rn.f32x2 %0, %1, %2;" : "=l"(r) : "l"(a), "l"(b)); return r;
}
__device__ __forceinline__ u64 fma2(u64 a, u64 b, u64 c) {
    u64 r; asm("fma.rn.f32x2 %0, %1, %2, %3;" : "=l"(r) : "l"(a), "l"(b), "l"(c)); return r;
}
__device__ __forceinline__ void unpack2(u64 v, float& lo, float& hi) {
    asm("mov.b64 {%0, %1}, %2;" : "=f"(lo), "=f"(hi) : "l"(v));
}
// lerp(a,b,w) = a*uw + b*w, with uw = (1-w) premasked by validity
__device__ __forceinline__ u64 lerp2(u64 a, u64 b, u64 uw, u64 w) {
    return fma2(a, uw, mul2(b, w));
}

__global__ void __launch_bounds__(128, 11)
roi_pool_kernel(const float* __restrict__ fm,
                const float* __restrict__ rois,
                float* __restrict__ out) {
    const int blk = blockIdx.x;             // 0 .. 256*7-1 = n*7 + ph
    const int n  = blk / POOLED;
    const int ph = blk - n * POOLED;
    const int b  = n >> 7;

    // rois flat: n*4 + {0:x1, 1:y1, 2:x2, 3:y2} (after reference's [1,0,3,2] perm)
    const float4 rr = __ldg((const float4*)rois + n);
    const float sy = (rr.w - rr.y) * (float)(HH - 1) / (float)(CROP - 1);
    const float sx = (rr.z - rr.x) * (float)(WW - 1) / (float)(CROP - 1);
    const float by = rr.y * (float)(HH - 1);
    const float bx = rr.x * (float)(WW - 1);

    // ---- per-(n,ph) y setup, amortized over 7 pw cells ----
    int y0i[KSIZE], y1i[KSIZE];
    u64 wy2[KSIZE], uy2[KSIZE];
#pragma unroll
    for (int ky = 0; ky < KSIZE; ky++) {
        const float i  = (float)(KSIZE * ph + ky);
        const float ys = by + i * sy;
        const float m  = ((ys >= 0.0f) && (ys <= (float)(HH - 1))) ? 1.0f : 0.0f;
        const float y0f = floorf(ys);
        const float w   = ys - y0f;
        wy2[ky] = pack2(w * m);
        uy2[ky] = pack2((1.0f - w) * m);
        int y0 = (int)y0f;
        y0 = min(max(y0, 0), HH - 1);
        y0i[ky] = y0;
        y1i[ky] = min(y0 + 1, HH - 1);
    }

    const int c4 = threadIdx.x;
    const ulonglong2* __restrict__ base =
        (const ulonglong2*)fm + b * (HH * WW * C4) + c4;
    // 4 row pointers, hoisted out of the pw loop
    const ulonglong2* __restrict__ R0 = base + y0i[0] * (WW * C4);
    const ulonglong2* __restrict__ R1 = base + y1i[0] * (WW * C4);
    const ulonglong2* __restrict__ R2 = base + y0i[1] * (WW * C4);
    const ulonglong2* __restrict__ R3 = base + y1i[1] * (WW * C4);

    float4* __restrict__ outp =
        (float4*)out + (blk * POOLED) * C4 + c4;

#pragma unroll 1
    for (int pw = 0; pw < POOLED; pw++) {
        // ---- per-pw x setup (validity folded into packed weights) ----
        int o0, o1, o2, o3;
        u64 wx2[KSIZE], ux2[KSIZE];
        {
            const float j  = (float)(KSIZE * pw);
            const float xs = bx + j * sx;
            const float m  = ((xs >= 0.0f) && (xs <= (float)(WW - 1))) ? 1.0f : 0.0f;
            const float x0f = floorf(xs);
            const float w   = xs - x0f;
            wx2[0] = pack2(w * m);
            ux2[0] = pack2((1.0f - w) * m);
            int x0 = (int)x0f;
            x0 = min(max(x0, 0), WW - 1);
            o0 = x0 * C4;
            o1 = min(x0 + 1, WW - 1) * C4;
        }
        {
            const float j  = (float)(KSIZE * pw + 1);
            const float xs = bx + j * sx;
            const float m  = ((xs >= 0.0f) && (xs <= (float)(WW - 1))) ? 1.0f : 0.0f;
            const float x0f = floorf(xs);
            const float w   = xs - x0f;
            wx2[1] = pack2(w * m);
            ux2[1] = pack2(1.0f - w * m - (1.0f - m)); // (1-w)*m, fewer temps
            int x0 = (int)x0f;
            x0 = min(max(x0, 0), WW - 1);
            o2 = x0 * C4;
            o3 = min(x0 + 1, WW - 1) * C4;
        }

        // ---- 16 independent 16B loads, all up front ----
        ulonglong2 p00 = R0[o0];
        ulonglong2 p01 = R0[o1];
        ulonglong2 p02 = R0[o2];
        ulonglong2 p03 = R0[o3];
        ulonglong2 p10 = R1[o0];
        ulonglong2 p11 = R1[o1];
        ulonglong2 p12 = R1[o2];
        ulonglong2 p13 = R1[o3];
        ulonglong2 p20 = R2[o0];
        ulonglong2 p21 = R2[o1];
        ulonglong2 p22 = R2[o2];
        ulonglong2 p23 = R2[o3];
        ulonglong2 p30 = R3[o0];
        ulonglong2 p31 = R3[o1];
        ulonglong2 p32 = R3[o2];
        ulonglong2 p33 = R3[o3];

        float b0 = -__FLT_MAX__, b1 = -__FLT_MAX__,
              b2 = -__FLT_MAX__, b3 = -__FLT_MAX__;

        {   // ky0 kx0
            u64 t0l = lerp2(p00.x, p10.x, uy2[0], wy2[0]);
            u64 t0h = lerp2(p00.y, p10.y, uy2[0], wy2[0]);
            u64 t1l = lerp2(p01.x, p11.x, uy2[0], wy2[0]);
            u64 t1h = lerp2(p01.y, p11.y, uy2[0], wy2[0]);
            u64 vl  = lerp2(t0l, t1l, ux2[0], wx2[0]);
            u64 vh  = lerp2(t0h, t1h, ux2[0], wx2[0]);
            float f0, f1, f2, f3;
            unpack2(vl, f0, f1); unpack2(vh, f2, f3);
            b0 = fmaxf(b0, f0); b1 = fmaxf(b1, f1);
            b2 = fmaxf(b2, f2); b3 = fmaxf(b3, f3);
        }
        {   // ky0 kx1
            u64 t0l = lerp2(p02.x, p12.x, uy2[0], wy2[0]);
            u64 t0h = lerp2(p02.y, p12.y, uy2[0], wy2[0]);
            u64 t1l = lerp2(p03.x, p13.x, uy2[0], wy2[0]);
            u64 t1h = lerp2(p03.y, p13.y, uy2[0], wy2[0]);
            u64 vl  = lerp2(t0l, t1l, ux2[1], wx2[1]);
            u64 vh  = lerp2(t0h, t1h, ux2[1], wx2[1]);
            float f0, f1, f2, f3;
            unpack2(vl, f0, f1); unpack2(vh, f2, f3);
            b0 = fmaxf(b0, f0); b1 = fmaxf(b1, f1);
            b2 = fmaxf(b2, f2); b3 = fmaxf(b3, f3);
        }
        {   // ky1 kx0
            u64 t0l = lerp2(p20.x, p30.x, uy2[1], wy2[1]);
            u64 t0h = lerp2(p20.y, p30.y, uy2[1], wy2[1]);
            u64 t1l = lerp2(p21.x, p31.x, uy2[1], wy2[1]);
            u64 t1h = lerp2(p21.y, p31.y, uy2[1], wy2[1]);
            u64 vl  = lerp2(t0l, t1l, ux2[0], wx2[0]);
            u64 vh  = lerp2(t0h, t1h, ux2[0], wx2[0]);
            float f0, f1, f2, f3;
            unpack2(vl, f0, f1); unpack2(vh, f2, f3);
            b0 = fmaxf(b0, f0); b1 = fmaxf(b1, f1);
            b2 = fmaxf(b2, f2); b3 = fmaxf(b3, f3);
        }
        {   // ky1 kx1
            u64 t0l = lerp2(p22.x, p32.x, uy2[1], wy2[1]);
            u64 t0h = lerp2(p22.y, p32.y, uy2[1], wy2[1]);
            u64 t1l = lerp2(p23.x, p33.x, uy2[1], wy2[1]);
            u64 t1h = lerp2(p23.y, p33.y, uy2[1], wy2[1]);
            u64 vl  = lerp2(t0l, t1l, ux2[1], wx2[1]);
            u64 vh  = lerp2(t0h, t1h, ux2[1], wx2[1]);
            float f0, f1, f2, f3;
            unpack2(vl, f0, f1); unpack2(vh, f2, f3);
            b0 = fmaxf(b0, f0); b1 = fmaxf(b1, f1);
            b2 = fmaxf(b2, f2); b3 = fmaxf(b3, f3);
        }

        float4 res;
        res.x = b0; res.y = b1; res.z = b2; res.w = b3;
        outp[pw * C4] = res;
    }
}

extern "C" void kernel_launch(void* const* d_in, const int* in_sizes, int n_in,
                              void* d_out, int out_size) {
    const float* fm   = (const float*)d_in[0];   // (2,50,50,512) f32
    const float* rois = (const float*)d_in[1];   // (2,128,4) f32
    float* out = (float*)d_out;                  // (256,7,7,512) f32

    const int blocks = NROI * POOLED;            // 1792
    roi_pool_kernel<<<blocks, 128>>>(fm, rois, out);
}